// round 3
// baseline (speedup 1.0000x reference)
#include <cuda_runtime.h>

typedef unsigned long long ull;

// ---------------- scratch (no allocations allowed) ----------------
// gh buffer: (B*S=128, 2*hid=256, H*W=1024) floats, reused by both layers
__device__ float g_gh[33554432];     // 128 MB
// layer-0 output: (B=4, S=32, hid=128, 1024)
__device__ float g_out0[16777216];   // 64 MB
// transposed weights [cin][k][cout], sized for layer 1 (128*9*256)
__device__ float g_wT[294912];

// ---------------- packed f32x2 helpers ----------------
__device__ __forceinline__ ull pack2(float lo, float hi) {
    ull d;
    asm("mov.b64 %0, {%1, %2};" : "=l"(d)
        : "r"(__float_as_uint(lo)), "r"(__float_as_uint(hi)));
    return d;
}
__device__ __forceinline__ void unpack2(ull v, float& lo, float& hi) {
    unsigned a, b;
    asm("mov.b64 {%0, %1}, %2;" : "=r"(a), "=r"(b) : "l"(v));
    lo = __uint_as_float(a);
    hi = __uint_as_float(b);
}
__device__ __forceinline__ ull ffma2(ull a, ull b, ull c) {
    ull d;
    asm("fma.rn.f32x2 %0, %1, %2, %3;" : "=l"(d) : "l"(a), "l"(b), "l"(c));
    return d;
}

// ---------------- weight transpose: w[co][ci][k] -> wT[(ci*9+k)*256+co] ----
template <int CIN>
__global__ void wtrans_kernel(const float* __restrict__ w) {
    int idx = blockIdx.x * 256 + threadIdx.x;   // grid sized exactly CIN*9
    int co = idx & 255;
    int rest = idx >> 8;
    int k = rest % 9;
    int ci = rest / 9;
    g_wT[idx] = w[(co * CIN + ci) * 9 + k];
}

// ---------------- fused 3x3 conv (implicit, direct) ----------------
// Block: 64 cout x (4 rows x 32 cols) of one image (bs). 256 threads:
//   tp = tid & 15  -> pixel pair (cols 2tp, 2tp+1) in each of the 4 rows
//   tc = tid >> 4  -> cout channels {tc + 16*j, j=0..3}
// Accumulate over cin in chunks of 4 via packed FFMA2 (2 pixels / instr).
template <int CIN, bool XG>
__global__ void __launch_bounds__(256, 2)
conv_kernel(const float* __restrict__ xin, const float* __restrict__ bias) {
    const int bx = blockIdx.x;   // row band 0..7  (h0 = 4*bx)
    const int cb = blockIdx.y;   // cout block 0..3 (64 couts)
    const int bs = blockIdx.z;   // 0..127 (b*32+s)
    const int tid = threadIdx.x;
    const int tp = tid & 15;
    const int tc = tid >> 4;
    const int h0 = bx * 4;

    __shared__ float xs[4][6][36];   // 4 cin x (rows h0-1..h0+4) x (cols -1..34)
    __shared__ float ws[4][9][64];   // 4 cin x 9 taps x 64 couts

    const float* x = XG ? (const float*)g_out0 : xin;
    const float* xbase = x + (size_t)bs * CIN * 1024;

    ull acc[4][4];
#pragma unroll
    for (int co = 0; co < 4; co++) {
        float bv = bias[cb * 64 + tc + 16 * co];
        ull bp = pack2(bv, bv);
#pragma unroll
        for (int orow = 0; orow < 4; orow++) acc[orow][co] = bp;
    }

#pragma unroll 1
    for (int cin0 = 0; cin0 < CIN; cin0 += 4) {
        // ---- fill xs (with zero halo) ----
        for (int idx = tid; idx < 4 * 6 * 36; idx += 256) {
            int ci = idx / 216;
            int rem = idx - ci * 216;
            int row = rem / 36;
            int cc = rem - row * 36;
            int xr = h0 - 1 + row;
            int xc = cc - 1;
            float v = 0.0f;
            if (xr >= 0 && xr < 32 && xc >= 0 && xc < 32)
                v = xbase[((cin0 + ci) * 32 + xr) * 32 + xc];
            xs[ci][row][cc] = v;
        }
        // ---- fill ws from transposed weights (coalesced over cout) ----
        for (int idx = tid; idx < 4 * 9 * 64; idx += 256) {
            int ci = idx / 576;
            int rem = idx - ci * 576;
            int k = rem / 64;
            int co = rem - k * 64;
            ws[ci][k][co] = g_wT[((cin0 + ci) * 9 + k) * 256 + cb * 64 + co];
        }
        __syncthreads();

#pragma unroll 1
        for (int ci = 0; ci < 4; ci++) {
#pragma unroll
            for (int r = 0; r < 3; r++) {
                ull wp[3][4];
#pragma unroll
                for (int c = 0; c < 3; c++) {
#pragma unroll
                    for (int co = 0; co < 4; co++) {
                        float wv = ws[ci][r * 3 + c][tc + 16 * co];
                        wp[c][co] = pack2(wv, wv);
                    }
                }
#pragma unroll
                for (int orow = 0; orow < 4; orow++) {
                    const float* xr = xs[ci][orow + r];
                    float2 va = *reinterpret_cast<const float2*>(xr + 2 * tp);
                    float2 vb = *reinterpret_cast<const float2*>(xr + 2 * tp + 2);
                    ull p0 = pack2(va.x, va.y);
                    ull p1 = pack2(va.y, vb.x);
                    ull p2 = pack2(vb.x, vb.y);
#pragma unroll
                    for (int co = 0; co < 4; co++)
                        acc[orow][co] = ffma2(p0, wp[0][co], acc[orow][co]);
#pragma unroll
                    for (int co = 0; co < 4; co++)
                        acc[orow][co] = ffma2(p1, wp[1][co], acc[orow][co]);
#pragma unroll
                    for (int co = 0; co < 4; co++)
                        acc[orow][co] = ffma2(p2, wp[2][co], acc[orow][co]);
                }
            }
        }
        __syncthreads();
    }

    // ---- store gh tile ----
    float* obase = g_gh + ((size_t)bs * 256 + cb * 64) * 1024 + h0 * 32;
#pragma unroll
    for (int co = 0; co < 4; co++) {
#pragma unroll
        for (int orow = 0; orow < 4; orow++) {
            float lo, hi;
            unpack2(acc[orow][co], lo, hi);
            float2 v = make_float2(lo, hi);
            *reinterpret_cast<float2*>(
                &obase[(tc + 16 * co) * 1024 + orow * 32 + 2 * tp]) = v;
        }
    }
}

// ---------------- minGRU sequential scan over S=32 ----------------
// h_t = (1 - z_t) h_{t-1} + z_t g(hidden_t), h0 = 0.5
// z = sigmoid(gate);  g(x) = x + 0.5 (x>=0) else sigmoid(x)
// LAYER 0 writes g_out0 + final slot 0; LAYER 1 writes dout + final slot 1.
template <int LAYER>
__global__ void scan_kernel(float* __restrict__ dout) {
    int u = blockIdx.x * 256 + threadIdx.x;   // (b, c, p): 4*128*1024 threads
    int p = u & 1023;
    int c = (u >> 10) & 127;
    int b = u >> 17;

    const float* gptr = g_gh + ((size_t)(b * 32) * 256 + c) * 1024 + p;
    float* optr = (LAYER == 0 ? g_out0 : dout) +
                  ((size_t)(b * 32) * 128 + c) * 1024 + p;

    float h = 0.5f;
#pragma unroll 4
    for (int s = 0; s < 32; s++) {
        float gate = gptr[0];
        float hd = gptr[131072];       // +128*1024: hidden half of gh
        gptr += 262144;                // next s
        float z = 1.0f / (1.0f + __expf(-gate));
        float g = (hd >= 0.0f) ? (hd + 0.5f) : 1.0f / (1.0f + __expf(-hd));
        h += z * (g - h);
        *optr = h;
        optr += 131072;                // next s in out
    }
    // stacked finals: (2, B, 1, hid, H, W) after the main output
    dout[16777216 + LAYER * 524288 + u] = h;
}

// ---------------- launch ----------------
extern "C" void kernel_launch(void* const* d_in, const int* in_sizes, int n_in,
                              void* d_out, int out_size) {
    const float* x  = (const float*)d_in[0];
    const float* w0 = (const float*)d_in[1];
    const float* b0 = (const float*)d_in[2];
    const float* w1 = (const float*)d_in[3];
    const float* b1 = (const float*)d_in[4];
    float* out = (float*)d_out;

    // layer 0
    wtrans_kernel<64><<<64 * 9, 256>>>(w0);
    conv_kernel<64, false><<<dim3(8, 4, 128), 256>>>(x, b0);
    scan_kernel<0><<<2048, 256>>>(out);
    // layer 1 (input = g_out0)
    wtrans_kernel<128><<<128 * 9, 256>>>(w1);
    conv_kernel<128, true><<<dim3(8, 4, 128), 256>>>(nullptr, b1);
    scan_kernel<1><<<2048, 256>>>(out);
}